// round 4
// baseline (speedup 1.0000x reference)
#include <cuda_runtime.h>

#define HH 56
#define WW 56
#define PP 3136   // HH*WW
#define BB 8
#define CC 64
#define KK 9      // 3x3
#define CHUNK 170 // ceil(8*3136 / 148)

// Scratch (device globals: no allocation allowed in kernel_launch)
__device__ float g_xT[BB * PP * CC];    // x transposed: [b][p][c], c contiguous
__device__ float g_invn[BB * PP];       // 1/||x[b,:,p]||
__device__ int   g_sel[BB * PP * KK];   // sorted selected pixel indices

// ---------------------------------------------------------------------------
// packed dual-FP32 FMA (Blackwell f32x2 path)
// ---------------------------------------------------------------------------
__device__ __forceinline__ float2 ffma2(float2 a, float2 b, float2 c) {
    unsigned long long A, Bv, Cv;
    A  = *reinterpret_cast<unsigned long long*>(&a);
    Bv = *reinterpret_cast<unsigned long long*>(&b);
    Cv = *reinterpret_cast<unsigned long long*>(&c);
    unsigned long long R;
    asm("fma.rn.f32x2 %0, %1, %2, %3;" : "=l"(R) : "l"(A), "l"(Bv), "l"(Cv));
    return *reinterpret_cast<float2*>(&R);
}

// ---------------------------------------------------------------------------
// 1) transpose x[b][c][p] -> xT[b][p][c]
// ---------------------------------------------------------------------------
__global__ void transpose_kernel(const float* __restrict__ x) {
    __shared__ float t[32][33];
    int b  = blockIdx.z;
    int p0 = blockIdx.x * 32;   // 3136 = 98*32 exact
    int c0 = blockIdx.y * 32;   // 64 = 2*32 exact
    const float* xb = x + (size_t)b * CC * PP;
    float* xTb = g_xT + (size_t)b * PP * CC;
    int tx = threadIdx.x, ty = threadIdx.y;
#pragma unroll
    for (int r = 0; r < 32; r += 8)
        t[ty + r][tx] = xb[(c0 + ty + r) * PP + p0 + tx];
    __syncthreads();
#pragma unroll
    for (int r = 0; r < 32; r += 8)
        xTb[(p0 + ty + r) * CC + c0 + tx] = t[tx][ty + r];
}

// ---------------------------------------------------------------------------
// 2) inverse L2 norm per pixel (warp per pixel)
// ---------------------------------------------------------------------------
__global__ void invnorm_kernel() {
    int gw = (blockIdx.x * blockDim.x + threadIdx.x) >> 5;
    int lane = threadIdx.x & 31;
    if (gw >= BB * PP) return;
    const float* row = g_xT + (size_t)gw * CC;
    float v0 = row[lane], v1 = row[lane + 32];
    float s = v0 * v0 + v1 * v1;
#pragma unroll
    for (int o = 16; o; o >>= 1) s += __shfl_xor_sync(0xffffffffu, s, o);
    if (lane == 0) g_invn[gw] = 1.0f / sqrtf(s);
}

// ---------------------------------------------------------------------------
// 3) cosine sims over clipped 5x5 window, pick 9 smallest (top_k(-sims)),
//    write indices sorted ascending. One warp per pixel.
// ---------------------------------------------------------------------------
__global__ void simsel_kernel() {
    int gw = (blockIdx.x * blockDim.x + threadIdx.x) >> 5;
    int lane = threadIdx.x & 31;
    if (gw >= BB * PP) return;
    int b = gw / PP, p = gw % PP;
    int i = p / WW, j = p % WW;
    const float* xb = g_xT + (size_t)b * PP * CC;
    const float* invb = g_invn + b * PP;

    float xc0 = xb[p * CC + lane];
    float xc1 = xb[p * CC + 32 + lane];
    float icn = invb[p];

    const float INF = __int_as_float(0x7f800000);
    float mysim = INF;           // lane k holds sim of candidate slot k
    int   mycand = 0x7fffffff;

    int lo_i = (i - 2 < 0) ? 0 : i - 2;
    int hi_i = (i + 2 > HH - 1) ? HH - 1 : i + 2;
    int lo_j = (j - 2 < 0) ? 0 : j - 2;
    int hi_j = (j + 2 > WW - 1) ? WW - 1 : j + 2;

    int slot = 0;
    for (int ii = lo_i; ii <= hi_i; ii++) {
        for (int jj = lo_j; jj <= hi_j; jj++) {
            int cp = ii * WW + jj;
            float a0 = xb[cp * CC + lane];
            float a1 = xb[cp * CC + 32 + lane];
            float part = xc0 * a0 + xc1 * a1;
#pragma unroll
            for (int o = 16; o; o >>= 1)
                part += __shfl_xor_sync(0xffffffffu, part, o);
            float sim = part * icn * invb[cp];
            if (lane == slot) { mysim = sim; mycand = cp; }
            slot++;
        }
    }

    // 9 rounds of warp argmin with (value, lane) tie-break (lower slot wins,
    // matching jax.lax.top_k stability). Lane r keeps the r-th pick.
    float v = mysim;
    int mypick = 0x7fffffff;
#pragma unroll
    for (int r = 0; r < KK; r++) {
        float bv = v; int bl = lane;
#pragma unroll
        for (int o = 16; o; o >>= 1) {
            float ov = __shfl_xor_sync(0xffffffffu, bv, o);
            int   ol = __shfl_xor_sync(0xffffffffu, bl, o);
            if (ov < bv || (ov == bv && ol < bl)) { bv = ov; bl = ol; }
        }
        int wc = __shfl_sync(0xffffffffu, mycand, bl);
        if (lane == r) mypick = wc;
        if (lane == bl) v = INF;
    }

    // rank = #selected indices smaller than mine -> writes sorted ascending
    int rank = 0;
#pragma unroll
    for (int r = 0; r < KK; r++) {
        int other = __shfl_sync(0xffffffffu, mypick, r);
        if (lane < KK && r != lane && other < mypick) rank++;
    }
    if (lane < KK) g_sel[(size_t)gw * KK + rank] = mypick;
}

// ---------------------------------------------------------------------------
// 4) gathered conv: out[b,o,p] = sum_{c,k} w[o,c,k] * xT[b, sel[b,p,k], c]
//    512 threads = 64 o x 8 c-groups; weights register-cached per block;
//    gathered x double-buffered in smem; packed f32x2 FMAs.
// ---------------------------------------------------------------------------
__global__ void __launch_bounds__(512, 1)
conv_kernel(const float* __restrict__ wgt, float* __restrict__ out) {
    // xg declared FIRST and 16B-aligned: float4 loads from it require the
    // base to be 16-aligned (selS is 6120 bytes = 8 mod 16, which previously
    // pushed xg off alignment -> misaligned LDS.128 trap).
    __shared__ __align__(16) float xg[2][KK][96]; // per k: 8 groups of 8 floats @ stride 12
    __shared__ int selS[CHUNK * KK];

    int tid = threadIdx.x;
    int o = tid >> 3;     // output channel 0..63
    int g = tid & 7;      // c-group 0..7 (channels g*8 .. g*8+7)

    int q0 = blockIdx.x * CHUNK;
    int npix = BB * PP - q0;
    if (npix > CHUNK) npix = CHUNK;
    if (npix <= 0) return;

    // register-cache weights: w[o][g*8+2i(+1)][k] as float2 pairs
    float2 wp[KK][4];
#pragma unroll
    for (int k = 0; k < KK; k++)
#pragma unroll
        for (int i = 0; i < 4; i++) {
            int c = g * 8 + 2 * i;
            wp[k][i].x = wgt[o * 576 + c * 9 + k];
            wp[k][i].y = wgt[o * 576 + (c + 1) * 9 + k];
        }

    for (int t = tid; t < npix * KK; t += 512) selS[t] = g_sel[q0 * KK + t];
    __syncthreads();

    // each thread stages gather element e0=tid (k0,c0); threads <64 also e1 (k=8,c=tid)
    int k0 = tid >> 6, c0 = tid & 63;
    int soff0 = k0 * 96 + (c0 >> 3) * 12 + (c0 & 7);
    int soff1 = 8 * 96 + (tid >> 3) * 12 + (tid & 7);

    float pr0 = 0.0f, pr1 = 0.0f;
    {   // prefetch pixel 0
        int q = q0;
        int b = q / PP;
        const float* xb = g_xT + (size_t)b * PP * CC;
        pr0 = xb[selS[k0] * CC + c0];
        if (tid < 64) pr1 = xb[selS[8] * CC + tid];
    }

    for (int n = 0; n < npix; n++) {
        int cur = n & 1;
        float* buf = &xg[cur][0][0];
        buf[soff0] = pr0;
        if (tid < 64) buf[soff1] = pr1;
        __syncthreads();

        if (n + 1 < npix) {  // prefetch next pixel (overlaps with compute)
            int q = q0 + n + 1;
            int b = q / PP;
            const float* xb = g_xT + (size_t)b * PP * CC;
            pr0 = xb[selS[(n + 1) * KK + k0] * CC + c0];
            if (tid < 64) pr1 = xb[selS[(n + 1) * KK + 8] * CC + tid];
        }

        float2 acc; acc.x = 0.0f; acc.y = 0.0f;
#pragma unroll
        for (int k = 0; k < KK; k++) {
            const float4* r4 = (const float4*)(buf + k * 96 + g * 12);
            float4 a = r4[0];
            float4 b4 = r4[1];
            float2 t0; t0.x = a.x;  t0.y = a.y;
            float2 t1; t1.x = a.z;  t1.y = a.w;
            float2 t2; t2.x = b4.x; t2.y = b4.y;
            float2 t3; t3.x = b4.z; t3.y = b4.w;
            acc = ffma2(wp[k][0], t0, acc);
            acc = ffma2(wp[k][1], t1, acc);
            acc = ffma2(wp[k][2], t2, acc);
            acc = ffma2(wp[k][3], t3, acc);
        }
        float s = acc.x + acc.y;
        s += __shfl_xor_sync(0xffffffffu, s, 4);
        s += __shfl_xor_sync(0xffffffffu, s, 2);
        s += __shfl_xor_sync(0xffffffffu, s, 1);
        if (g == 0) {
            int q = q0 + n;
            int b = q / PP, pp = q % PP;
            out[((size_t)b * CC + o) * PP + pp] = s;
        }
    }
}

// ---------------------------------------------------------------------------
extern "C" void kernel_launch(void* const* d_in, const int* in_sizes, int n_in,
                              void* d_out, int out_size) {
    const float* x = (const float*)d_in[0];   // [8,64,56,56]
    const float* w = (const float*)d_in[1];   // [64,64,3,3]
    float* out = (float*)d_out;               // [8,64,56,56]

    transpose_kernel<<<dim3(98, 2, 8), dim3(32, 8)>>>(x);
    invnorm_kernel<<<(BB * PP * 32 + 255) / 256, 256>>>();
    simsel_kernel<<<(BB * PP) / 8, 256>>>();
    conv_kernel<<<148, 512>>>(w, out);
}

// round 5
// speedup vs baseline: 2.7530x; 2.7530x over previous
#include <cuda_runtime.h>

#define HH 56
#define WW 56
#define PP 3136   // HH*WW
#define BB 8
#define CC 64
#define KK 9      // 3x3

// Scratch (device globals: no allocation allowed in kernel_launch)
__device__ float g_xT[BB * PP * CC];    // x transposed: [b][p][c], c contiguous
__device__ float g_invn[BB * PP];       // 1/||x[b,:,p]||
__device__ int   g_sel[BB * PP * KK];   // sorted selected pixel indices
__device__ float g_wP[KK * 64 * 64];    // W reordered: [k][m][o], c = 4*(m&15)+(m>>4)

// ---------------------------------------------------------------------------
// packed dual-FP32 FMA (Blackwell f32x2 path)
// ---------------------------------------------------------------------------
__device__ __forceinline__ float2 ffma2(float2 a, float2 b, float2 c) {
    unsigned long long A, Bv, Cv;
    A  = *reinterpret_cast<unsigned long long*>(&a);
    Bv = *reinterpret_cast<unsigned long long*>(&b);
    Cv = *reinterpret_cast<unsigned long long*>(&c);
    unsigned long long R;
    asm("fma.rn.f32x2 %0, %1, %2, %3;" : "=l"(R) : "l"(A), "l"(Bv), "l"(Cv));
    return *reinterpret_cast<float2*>(&R);
}

__device__ __forceinline__ void cp16(void* sdst, const void* gsrc) {
    unsigned sa = (unsigned)__cvta_generic_to_shared(sdst);
    asm volatile("cp.async.cg.shared.global [%0], [%1], 16;\n" :: "r"(sa), "l"(gsrc));
}

// ---------------------------------------------------------------------------
// 1) transpose x[b][c][p] -> xT[b][p][c]
// ---------------------------------------------------------------------------
__global__ void transpose_kernel(const float* __restrict__ x) {
    __shared__ float t[32][33];
    int b  = blockIdx.z;
    int p0 = blockIdx.x * 32;   // 3136 = 98*32 exact
    int c0 = blockIdx.y * 32;   // 64 = 2*32 exact
    const float* xb = x + (size_t)b * CC * PP;
    float* xTb = g_xT + (size_t)b * PP * CC;
    int tx = threadIdx.x, ty = threadIdx.y;
#pragma unroll
    for (int r = 0; r < 32; r += 8)
        t[ty + r][tx] = xb[(c0 + ty + r) * PP + p0 + tx];
    __syncthreads();
#pragma unroll
    for (int r = 0; r < 32; r += 8)
        xTb[(p0 + ty + r) * CC + c0 + tx] = t[tx][ty + r];
}

// ---------------------------------------------------------------------------
// 1b) reorder weights: g_wP[k][m][o] = w[o][c(m)][k],  c(m)=4*(m&15)+(m>>4)
// ---------------------------------------------------------------------------
__global__ void wprep_kernel(const float* __restrict__ wgt) {
    int i = blockIdx.x * 256 + threadIdx.x;
    if (i >= KK * 64 * 64) return;
    int k = i >> 12, r = i & 4095, m = r >> 6, o = r & 63;
    int c = 4 * (m & 15) + (m >> 4);
    g_wP[i] = wgt[o * 576 + c * 9 + k];
}

// ---------------------------------------------------------------------------
// 2) inverse L2 norm per pixel (warp per pixel)
// ---------------------------------------------------------------------------
__global__ void invnorm_kernel() {
    int gw = (blockIdx.x * blockDim.x + threadIdx.x) >> 5;
    int lane = threadIdx.x & 31;
    if (gw >= BB * PP) return;
    const float* row = g_xT + (size_t)gw * CC;
    float v0 = row[lane], v1 = row[lane + 32];
    float s = v0 * v0 + v1 * v1;
#pragma unroll
    for (int o = 16; o; o >>= 1) s += __shfl_xor_sync(0xffffffffu, s, o);
    if (lane == 0) g_invn[gw] = 1.0f / sqrtf(s);
}

// ---------------------------------------------------------------------------
// 3) cosine sims over clipped 5x5 window, pick 9 smallest (top_k(-sims)),
//    write indices sorted ascending. One warp per pixel.
// ---------------------------------------------------------------------------
__global__ void simsel_kernel() {
    int gw = (blockIdx.x * blockDim.x + threadIdx.x) >> 5;
    int lane = threadIdx.x & 31;
    if (gw >= BB * PP) return;
    int b = gw / PP, p = gw % PP;
    int i = p / WW, j = p % WW;
    const float* xb = g_xT + (size_t)b * PP * CC;
    const float* invb = g_invn + b * PP;

    float xc0 = xb[p * CC + lane];
    float xc1 = xb[p * CC + 32 + lane];
    float icn = invb[p];

    const float INF = __int_as_float(0x7f800000);
    float mysim = INF;           // lane k holds sim of candidate slot k
    int   mycand = 0x7fffffff;

    int lo_i = (i - 2 < 0) ? 0 : i - 2;
    int hi_i = (i + 2 > HH - 1) ? HH - 1 : i + 2;
    int lo_j = (j - 2 < 0) ? 0 : j - 2;
    int hi_j = (j + 2 > WW - 1) ? WW - 1 : j + 2;

    int slot = 0;
    for (int ii = lo_i; ii <= hi_i; ii++) {
        for (int jj = lo_j; jj <= hi_j; jj++) {
            int cp = ii * WW + jj;
            float a0 = xb[cp * CC + lane];
            float a1 = xb[cp * CC + 32 + lane];
            float part = xc0 * a0 + xc1 * a1;
#pragma unroll
            for (int o = 16; o; o >>= 1)
                part += __shfl_xor_sync(0xffffffffu, part, o);
            float sim = part * icn * invb[cp];
            if (lane == slot) { mysim = sim; mycand = cp; }
            slot++;
        }
    }

    // 9 rounds of warp argmin with (value, lane) tie-break
    float v = mysim;
    int mypick = 0x7fffffff;
#pragma unroll
    for (int r = 0; r < KK; r++) {
        float bv = v; int bl = lane;
#pragma unroll
        for (int o = 16; o; o >>= 1) {
            float ov = __shfl_xor_sync(0xffffffffu, bv, o);
            int   ol = __shfl_xor_sync(0xffffffffu, bl, o);
            if (ov < bv || (ov == bv && ol < bl)) { bv = ov; bl = ol; }
        }
        int wc = __shfl_sync(0xffffffffu, mycand, bl);
        if (lane == r) mypick = wc;
        if (lane == bl) v = INF;
    }

    int rank = 0;
#pragma unroll
    for (int r = 0; r < KK; r++) {
        int other = __shfl_sync(0xffffffffu, mypick, r);
        if (lane < KK && r != lane && other < mypick) rank++;
    }
    if (lane < KK) g_sel[(size_t)gw * KK + rank] = mypick;
}

// ---------------------------------------------------------------------------
// 4) gathered conv as register-blocked SGEMM:
//    out[b,o,q] = sum_{k-chunk kc} sum_m Ws[kc][m][o] * Gd[m][q]
//    Gd[m][q] = xT[b, sel[q][kc], c(m)]  (stored duplicated {g,g} for f32x2)
//    Tile 64o x 64q, 128 threads, thread tile 8o(4 f32x2 pairs) x 4q.
// ---------------------------------------------------------------------------
#define GQ 65          // float2 row stride of Gd (pad)
#define SEL_B 2304     // 576 ints
#define WS_B  32768    // 2 x 4096 floats
#define SMEM_TOTAL (SEL_B + WS_B + 2 * 64 * GQ * 8)

__global__ void __launch_bounds__(128)
conv2_kernel(float* __restrict__ out) {
    extern __shared__ char smem_raw[];
    int*    selS  = (int*)smem_raw;
    float*  WsAll = (float*)(smem_raw + SEL_B);
    float2* GdAll = (float2*)(smem_raw + SEL_B + WS_B);

    const int tid = threadIdx.x;
    const int tile = blockIdx.x;           // 392 tiles of 64 q
    const int qg0 = tile * 64;
    const int b = tile / 49;               // 3136/64 = 49 tiles per batch
    const int p0 = (tile % 49) * 64;
    const float* xb = g_xT + (size_t)b * PP * CC;

    // sel for this tile: 64 pixels x 9
    for (int t = tid; t < 64 * KK; t += 128) selS[t] = g_sel[(size_t)qg0 * KK + t];
    __syncthreads();

    const int u = tid & 15, qr = tid >> 4;   // staging role: row-of-8, c-float4 u

    // --- staging helpers ---
    float4 pg[8];
    // G gather prefetch for chunk kc (fully coalesced: 16 lanes per 256B row)
    auto ldG = [&](int kc) {
#pragma unroll
        for (int ps = 0; ps < 8; ps++) {
            int q = ps * 8 + qr;
            int row = selS[q * KK + kc];
            pg[ps] = *(const float4*)(xb + (size_t)row * CC + u * 4);
        }
    };
    auto stG = [&](int bufi) {
        float2* Gd = GdAll + bufi * (64 * GQ);
#pragma unroll
        for (int ps = 0; ps < 8; ps++) {
            int q = ps * 8 + qr;
            float4 v = pg[ps];
            Gd[(u      ) * GQ + q] = make_float2(v.x, v.x);   // m = 16*0+u
            Gd[(16 + u ) * GQ + q] = make_float2(v.y, v.y);   // m = 16*1+u
            Gd[(32 + u ) * GQ + q] = make_float2(v.z, v.z);
            Gd[(48 + u ) * GQ + q] = make_float2(v.w, v.w);
        }
    };
    auto cpW = [&](int kc, int bufi) {
        const float* src = g_wP + kc * 4096;
        float* dst = WsAll + bufi * 4096;
#pragma unroll
        for (int i = 0; i < 8; i++) {
            int e = (tid + i * 128) * 4;           // float4 granularity
            cp16(dst + e, src + e);
        }
        asm volatile("cp.async.commit_group;\n");
    };

    // --- compute fragment mapping ---
    const int w = tid >> 5, l = tid & 31;
    const int o0 = w * 16 + (l >> 4) * 8;  // 8 consecutive o
    const int qs = l & 15;                 // q = qs + 16*i

    float2 acc[4][4];
#pragma unroll
    for (int j = 0; j < 4; j++)
#pragma unroll
        for (int i = 0; i < 4; i++) acc[j][i] = make_float2(0.f, 0.f);

    // prologue
    ldG(0);
    cpW(0, 0);

    for (int kc = 0; kc < KK; kc++) {
        int bufi = kc & 1;
        asm volatile("cp.async.wait_group 0;\n");
        stG(bufi);
        __syncthreads();
        if (kc + 1 < KK) {
            ldG(kc + 1);
            cpW(kc + 1, bufi ^ 1);
        }
        const float*  Ws = WsAll + bufi * 4096;
        const float2* Gd = GdAll + bufi * (64 * GQ);
#pragma unroll 8
        for (int m = 0; m < 64; m++) {
            float4 w0 = *(const float4*)(Ws + m * 64 + o0);
            float4 w1 = *(const float4*)(Ws + m * 64 + o0 + 4);
            float2 wp0 = make_float2(w0.x, w0.y);
            float2 wp1 = make_float2(w0.z, w0.w);
            float2 wp2 = make_float2(w1.x, w1.y);
            float2 wp3 = make_float2(w1.z, w1.w);
#pragma unroll
            for (int i = 0; i < 4; i++) {
                float2 g = Gd[m * GQ + qs + 16 * i];
                acc[0][i] = ffma2(wp0, g, acc[0][i]);
                acc[1][i] = ffma2(wp1, g, acc[1][i]);
                acc[2][i] = ffma2(wp2, g, acc[2][i]);
                acc[3][i] = ffma2(wp3, g, acc[3][i]);
            }
        }
        __syncthreads();  // guard Gd/Ws buffer reuse (kc+2 staging)
    }

    // epilogue: out[b][o][p]
    float* ob = out + ((size_t)b * CC) * PP;
#pragma unroll
    for (int j = 0; j < 4; j++) {
        int oa = o0 + 2 * j;
#pragma unroll
        for (int i = 0; i < 4; i++) {
            int p = p0 + qs + 16 * i;
            ob[(size_t)oa * PP + p]       = acc[j][i].x;
            ob[(size_t)(oa + 1) * PP + p] = acc[j][i].y;
        }
    }
}

// ---------------------------------------------------------------------------
extern "C" void kernel_launch(void* const* d_in, const int* in_sizes, int n_in,
                              void* d_out, int out_size) {
    const float* x = (const float*)d_in[0];   // [8,64,56,56]
    const float* w = (const float*)d_in[1];   // [64,64,3,3]
    float* out = (float*)d_out;               // [8,64,56,56]

    cudaFuncSetAttribute(conv2_kernel,
                         cudaFuncAttributeMaxDynamicSharedMemorySize, SMEM_TOTAL);

    transpose_kernel<<<dim3(98, 2, 8), dim3(32, 8)>>>(x);
    wprep_kernel<<<(KK * 64 * 64 + 255) / 256, 256>>>(w);
    invnorm_kernel<<<(BB * PP * 32 + 255) / 256, 256>>>();
    simsel_kernel<<<(BB * PP) / 8, 256>>>();
    conv2_kernel<<<392, 128, SMEM_TOTAL>>>(out);
}

// round 6
// speedup vs baseline: 3.5088x; 1.2745x over previous
#include <cuda_runtime.h>

#define HH 56
#define WW 56
#define PP 3136   // HH*WW
#define BB 8
#define CC 64
#define KK 9      // 3x3

// Scratch (device globals: no allocation allowed in kernel_launch)
__device__ float g_xT[BB * PP * CC];    // x transposed: [b][p][c], c contiguous
__device__ float g_invn[BB * PP];       // 1/||x[b,:,p]||
__device__ int   g_sel[BB * PP * KK];   // sorted selected pixel indices
__device__ float g_wP[KK * 64 * 64];    // W reordered: [k][m][o], c = 4*(m&15)+(m>>4)

// ---------------------------------------------------------------------------
// packed dual-FP32 FMA (Blackwell f32x2 path)
// ---------------------------------------------------------------------------
__device__ __forceinline__ float2 ffma2(float2 a, float2 b, float2 c) {
    unsigned long long A, Bv, Cv;
    A  = *reinterpret_cast<unsigned long long*>(&a);
    Bv = *reinterpret_cast<unsigned long long*>(&b);
    Cv = *reinterpret_cast<unsigned long long*>(&c);
    unsigned long long R;
    asm("fma.rn.f32x2 %0, %1, %2, %3;" : "=l"(R) : "l"(A), "l"(Bv), "l"(Cv));
    return *reinterpret_cast<float2*>(&R);
}

__device__ __forceinline__ void cp16(void* sdst, const void* gsrc) {
    unsigned sa = (unsigned)__cvta_generic_to_shared(sdst);
    asm volatile("cp.async.cg.shared.global [%0], [%1], 16;\n" :: "r"(sa), "l"(gsrc));
}

// ---------------------------------------------------------------------------
// 1) transpose x[b][c][p] -> xT[b][p][c]
// ---------------------------------------------------------------------------
__global__ void transpose_kernel(const float* __restrict__ x) {
    __shared__ float t[32][33];
    int b  = blockIdx.z;
    int p0 = blockIdx.x * 32;   // 3136 = 98*32 exact
    int c0 = blockIdx.y * 32;   // 64 = 2*32 exact
    const float* xb = x + (size_t)b * CC * PP;
    float* xTb = g_xT + (size_t)b * PP * CC;
    int tx = threadIdx.x, ty = threadIdx.y;
#pragma unroll
    for (int r = 0; r < 32; r += 8)
        t[ty + r][tx] = xb[(c0 + ty + r) * PP + p0 + tx];
    __syncthreads();
#pragma unroll
    for (int r = 0; r < 32; r += 8)
        xTb[(p0 + ty + r) * CC + c0 + tx] = t[tx][ty + r];
}

// ---------------------------------------------------------------------------
// 1b) reorder weights: g_wP[k][m][o] = w[o][c(m)][k],  c(m)=4*(m&15)+(m>>4)
// ---------------------------------------------------------------------------
__global__ void wprep_kernel(const float* __restrict__ wgt) {
    int i = blockIdx.x * 256 + threadIdx.x;
    if (i >= KK * 64 * 64) return;
    int k = i >> 12, r = i & 4095, m = r >> 6, o = r & 63;
    int c = 4 * (m & 15) + (m >> 4);
    g_wP[i] = wgt[o * 576 + c * 9 + k];
}

// ---------------------------------------------------------------------------
// 2) inverse L2 norm per pixel (warp per pixel)
// ---------------------------------------------------------------------------
__global__ void invnorm_kernel() {
    int gw = (blockIdx.x * blockDim.x + threadIdx.x) >> 5;
    int lane = threadIdx.x & 31;
    if (gw >= BB * PP) return;
    const float* row = g_xT + (size_t)gw * CC;
    float v0 = row[lane], v1 = row[lane + 32];
    float s = v0 * v0 + v1 * v1;
#pragma unroll
    for (int o = 16; o; o >>= 1) s += __shfl_xor_sync(0xffffffffu, s, o);
    if (lane == 0) g_invn[gw] = 1.0f / sqrtf(s);
}

// ---------------------------------------------------------------------------
// 3) simsel v2: block = 8 pixels of one image row; smem holds the 5x12 halo
//    of NORMALIZED vectors (sim = plain dot). Each warp owns one pixel;
//    lane l serially accumulates the full dot for candidate l (no reduction
//    shuffles). Top-9-smallest via ordered-int REDUX.MIN + ballot (lowest
//    lane on ties = top_k stability); indices written sorted ascending.
// ---------------------------------------------------------------------------
#define SROW 68   // smem row stride (floats); 17 float4s, coprime-ish with 32 banks

__global__ void __launch_bounds__(256)
simsel2_kernel() {
    __shared__ __align__(16) float sn[60 * SROW];

    const int t = threadIdx.x;
    const int j0 = blockIdx.x * 8;      // 56/8 = 7 exact
    const int i  = blockIdx.y;
    const int b  = blockIdx.z;
    const float* xb   = g_xT + (size_t)b * PP * CC;
    const float* invb = g_invn + b * PP;

    // --- stage normalized halo: slots (ri 0..4, rj 0..11) for rows i-2..i+2,
    //     cols j0-2..j0+9 (invalid slots left unwritten, never read) ---
    {
        int slot = t >> 2, q = t & 3;
        if (slot < 60) {
            int ri = slot / 12, rj = slot - ri * 12;
            int gi = i - 2 + ri, gj = j0 - 2 + rj;
            if (gi >= 0 && gi < HH && gj >= 0 && gj < WW) {
                int gp = gi * WW + gj;
                const float* src = xb + (size_t)gp * CC;
                float iv = invb[gp];
                float* dst = sn + slot * SROW;
#pragma unroll
                for (int s = 0; s < 4; s++) {
                    float4 v = *(const float4*)(src + (q + 4 * s) * 4);
                    v.x *= iv; v.y *= iv; v.z *= iv; v.w *= iv;
                    *(float4*)(dst + (q + 4 * s) * 4) = v;
                }
            }
        }
    }
    __syncthreads();

    const int lane = t & 31, w = t >> 5;
    const int j = j0 + w;

    int lo_i = (i - 2 < 0) ? 0 : i - 2;
    int hi_i = (i + 2 > HH - 1) ? HH - 1 : i + 2;
    int lo_j = (j - 2 < 0) ? 0 : j - 2;
    int hi_j = (j + 2 > WW - 1) ? WW - 1 : j + 2;
    int nrow = hi_i - lo_i + 1, ncol = hi_j - lo_j + 1;
    int ncand = nrow * ncol;

    // lane -> (cr, cc) row-major over the clipped window (exact div by mult)
    unsigned mult = (65536u + (unsigned)ncol - 1) / (unsigned)ncol;
    int cr = (int)(((unsigned)lane * mult) >> 16);
    int cc = lane - cr * ncol;
    int ri = (lo_i - (i - 2)) + cr;
    int rj = (lo_j - (j0 - 2)) + cc;
    int slot = ri * 12 + rj;
    if (lane >= ncand) slot = 0;
    int cpix = (lo_i + cr) * WW + (lo_j + cc);   // candidate pixel index

    const float* crow = sn + slot * SROW;
    const float* prow = sn + (2 * 12 + (w + 2)) * SROW;  // this pixel's slot

    float2 aA = make_float2(0.f, 0.f), aB = make_float2(0.f, 0.f);
#pragma unroll
    for (int s = 0; s < 16; s++) {
        float4 cv = *(const float4*)(crow + 4 * s);
        float4 pv = *(const float4*)(prow + 4 * s);
        aA = ffma2(make_float2(cv.x, cv.y), make_float2(pv.x, pv.y), aA);
        aB = ffma2(make_float2(cv.z, cv.w), make_float2(pv.z, pv.w), aB);
    }
    float sim = (aA.x + aB.x) + (aA.y + aB.y);

    // ordered-int key: monotonic bijection float order -> uint order
    unsigned ub = __float_as_uint(sim);
    unsigned key = (ub & 0x80000000u) ? ~ub : (ub | 0x80000000u);
    if (lane >= ncand) key = 0xFFFFFFFFu;

    int mypick = 0;
#pragma unroll
    for (int r = 0; r < KK; r++) {
        unsigned m = __reduce_min_sync(0xffffffffu, key);
        unsigned ball = __ballot_sync(0xffffffffu, key == m);
        int bl = __ffs(ball) - 1;                // lowest lane = lowest slot (stable)
        int wc = __shfl_sync(0xffffffffu, cpix, bl);
        if (lane == bl) key = 0xFFFFFFFFu;
        if (lane == r) mypick = wc;
    }

    // rank among the 9 picks -> write sorted ascending
    int rank = 0;
#pragma unroll
    for (int r = 0; r < KK; r++) {
        int other = __shfl_sync(0xffffffffu, mypick, r);
        if (lane < KK && r != lane && other < mypick) rank++;
    }
    if (lane < KK)
        g_sel[((size_t)(b * PP + i * WW + j)) * KK + rank] = mypick;
}

// ---------------------------------------------------------------------------
// 4) gathered conv as register-blocked SGEMM:
//    out[b,o,q] = sum_{k-chunk kc} sum_m Ws[kc][m][o] * Gd[m][q]
//    Gd[m][q] = xT[b, sel[q][kc], c(m)]  (stored duplicated {g,g} for f32x2)
//    Tile 64o x 64q, 128 threads, thread tile 8o(4 f32x2 pairs) x 4q.
// ---------------------------------------------------------------------------
#define GQ 65          // float2 row stride of Gd (pad)
#define SEL_B 2304     // 576 ints
#define WS_B  32768    // 2 x 4096 floats
#define SMEM_TOTAL (SEL_B + WS_B + 2 * 64 * GQ * 8)

__global__ void __launch_bounds__(128)
conv2_kernel(float* __restrict__ out) {
    extern __shared__ char smem_raw[];
    int*    selS  = (int*)smem_raw;
    float*  WsAll = (float*)(smem_raw + SEL_B);
    float2* GdAll = (float2*)(smem_raw + SEL_B + WS_B);

    const int tid = threadIdx.x;
    const int tile = blockIdx.x;           // 392 tiles of 64 q
    const int qg0 = tile * 64;
    const int b = tile / 49;               // 3136/64 = 49 tiles per batch
    const int p0 = (tile % 49) * 64;
    const float* xb = g_xT + (size_t)b * PP * CC;

    // sel for this tile: 64 pixels x 9
    for (int t = tid; t < 64 * KK; t += 128) selS[t] = g_sel[(size_t)qg0 * KK + t];
    __syncthreads();

    const int u = tid & 15, qr = tid >> 4;   // staging role: row-of-8, c-float4 u

    // --- staging helpers ---
    float4 pg[8];
    auto ldG = [&](int kc) {
#pragma unroll
        for (int ps = 0; ps < 8; ps++) {
            int q = ps * 8 + qr;
            int row = selS[q * KK + kc];
            pg[ps] = *(const float4*)(xb + (size_t)row * CC + u * 4);
        }
    };
    auto stG = [&](int bufi) {
        float2* Gd = GdAll + bufi * (64 * GQ);
#pragma unroll
        for (int ps = 0; ps < 8; ps++) {
            int q = ps * 8 + qr;
            float4 v = pg[ps];
            Gd[(u      ) * GQ + q] = make_float2(v.x, v.x);
            Gd[(16 + u ) * GQ + q] = make_float2(v.y, v.y);
            Gd[(32 + u ) * GQ + q] = make_float2(v.z, v.z);
            Gd[(48 + u ) * GQ + q] = make_float2(v.w, v.w);
        }
    };
    auto cpW = [&](int kc, int bufi) {
        const float* src = g_wP + kc * 4096;
        float* dst = WsAll + bufi * 4096;
#pragma unroll
        for (int i = 0; i < 8; i++) {
            int e = (tid + i * 128) * 4;
            cp16(dst + e, src + e);
        }
        asm volatile("cp.async.commit_group;\n");
    };

    const int w = tid >> 5, l = tid & 31;
    const int o0 = w * 16 + (l >> 4) * 8;
    const int qs = l & 15;

    float2 acc[4][4];
#pragma unroll
    for (int j = 0; j < 4; j++)
#pragma unroll
        for (int i = 0; i < 4; i++) acc[j][i] = make_float2(0.f, 0.f);

    ldG(0);
    cpW(0, 0);

    for (int kc = 0; kc < KK; kc++) {
        int bufi = kc & 1;
        asm volatile("cp.async.wait_group 0;\n");
        stG(bufi);
        __syncthreads();
        if (kc + 1 < KK) {
            ldG(kc + 1);
            cpW(kc + 1, bufi ^ 1);
        }
        const float*  Ws = WsAll + bufi * 4096;
        const float2* Gd = GdAll + bufi * (64 * GQ);
#pragma unroll 8
        for (int m = 0; m < 64; m++) {
            float4 w0 = *(const float4*)(Ws + m * 64 + o0);
            float4 w1 = *(const float4*)(Ws + m * 64 + o0 + 4);
            float2 wp0 = make_float2(w0.x, w0.y);
            float2 wp1 = make_float2(w0.z, w0.w);
            float2 wp2 = make_float2(w1.x, w1.y);
            float2 wp3 = make_float2(w1.z, w1.w);
#pragma unroll
            for (int i = 0; i < 4; i++) {
                float2 g = Gd[m * GQ + qs + 16 * i];
                acc[0][i] = ffma2(wp0, g, acc[0][i]);
                acc[1][i] = ffma2(wp1, g, acc[1][i]);
                acc[2][i] = ffma2(wp2, g, acc[2][i]);
                acc[3][i] = ffma2(wp3, g, acc[3][i]);
            }
        }
        __syncthreads();
    }

    float* ob = out + ((size_t)b * CC) * PP;
#pragma unroll
    for (int j = 0; j < 4; j++) {
        int oa = o0 + 2 * j;
#pragma unroll
        for (int i = 0; i < 4; i++) {
            int p = p0 + qs + 16 * i;
            ob[(size_t)oa * PP + p]       = acc[j][i].x;
            ob[(size_t)(oa + 1) * PP + p] = acc[j][i].y;
        }
    }
}

// ---------------------------------------------------------------------------
extern "C" void kernel_launch(void* const* d_in, const int* in_sizes, int n_in,
                              void* d_out, int out_size) {
    const float* x = (const float*)d_in[0];   // [8,64,56,56]
    const float* w = (const float*)d_in[1];   // [64,64,3,3]
    float* out = (float*)d_out;               // [8,64,56,56]

    cudaFuncSetAttribute(conv2_kernel,
                         cudaFuncAttributeMaxDynamicSharedMemorySize, SMEM_TOTAL);

    transpose_kernel<<<dim3(98, 2, 8), dim3(32, 8)>>>(x);
    wprep_kernel<<<(KK * 64 * 64 + 255) / 256, 256>>>(w);
    invnorm_kernel<<<(BB * PP * 32 + 255) / 256, 256>>>();
    simsel2_kernel<<<dim3(7, 56, 8), 256>>>();
    conv2_kernel<<<392, 128, SMEM_TOTAL>>>(out);
}

// round 7
// speedup vs baseline: 3.5262x; 1.0050x over previous
#include <cuda_runtime.h>

#define HH 56
#define WW 56
#define PP 3136   // HH*WW
#define BB 8
#define CC 64
#define KK 9      // 3x3

// Scratch (device globals: no allocation allowed in kernel_launch)
__device__ float g_xT[BB * PP * CC];    // x transposed: [b][p][c], c contiguous
__device__ float g_invn[BB * PP];       // 1/||x[b,:,p]||
__device__ int   g_sel[BB * PP * KK];   // sorted selected pixel indices
__device__ float g_wP[KK * 64 * 64];    // W reordered: [k][m][o], c = 4*(m&15)+(m>>4)

// ---------------------------------------------------------------------------
// packed dual-FP32 FMA (Blackwell f32x2 path)
// ---------------------------------------------------------------------------
__device__ __forceinline__ float2 ffma2(float2 a, float2 b, float2 c) {
    unsigned long long A, Bv, Cv;
    A  = *reinterpret_cast<unsigned long long*>(&a);
    Bv = *reinterpret_cast<unsigned long long*>(&b);
    Cv = *reinterpret_cast<unsigned long long*>(&c);
    unsigned long long R;
    asm("fma.rn.f32x2 %0, %1, %2, %3;" : "=l"(R) : "l"(A), "l"(Bv), "l"(Cv));
    return *reinterpret_cast<float2*>(&R);
}

__device__ __forceinline__ void cp16(void* sdst, const void* gsrc) {
    unsigned sa = (unsigned)__cvta_generic_to_shared(sdst);
    asm volatile("cp.async.cg.shared.global [%0], [%1], 16;\n" :: "r"(sa), "l"(gsrc));
}

// ---------------------------------------------------------------------------
// 1) fused prep: blocks [0,784) transpose x[b][c][p] -> xT[b][p][c] AND
//    compute g_invn from the smem tile; blocks [784,793) reorder weights.
// ---------------------------------------------------------------------------
__global__ void __launch_bounds__(256)
prep_kernel(const float* __restrict__ x, const float* __restrict__ wgt) {
    const int id = blockIdx.x;
    const int t = threadIdx.x;

    if (id >= 784) {            // --- wprep: one block per k ---
        int k = id - 784;
#pragma unroll
        for (int i = 0; i < 16; i++) {
            int r = t * 16 + i;            // 0..4095
            int m = r >> 6, o = r & 63;
            int c = 4 * (m & 15) + (m >> 4);
            g_wP[k * 4096 + r] = wgt[o * 576 + c * 9 + k];
        }
        return;
    }

    // --- transpose tile: 32 pixels x 64 channels ---
    __shared__ float s[64][37];   // stride 37: conflict-free access patterns
    int b = id / 98, pt = id - b * 98;
    int p0 = pt * 32;
    const float* xb = x + (size_t)b * CC * PP;
    float* xTb = g_xT + (size_t)b * PP * CC;

    int cl = t >> 3;        // 0..31
    int j4 = t & 7;         // float4 column within the 32 pixels
#pragma unroll
    for (int h = 0; h < 2; h++) {
        int c = cl + 32 * h;
        float4 v = *(const float4*)(xb + (size_t)c * PP + p0 + 4 * j4);
        s[c][4 * j4 + 0] = v.x; s[c][4 * j4 + 1] = v.y;
        s[c][4 * j4 + 2] = v.z; s[c][4 * j4 + 3] = v.w;
    }
    __syncthreads();

    int p = t >> 3, cq0 = t & 7;
#pragma unroll
    for (int h = 0; h < 2; h++) {
        int cq = cq0 + 8 * h;
        float4 v;
        v.x = s[4 * cq + 0][p]; v.y = s[4 * cq + 1][p];
        v.z = s[4 * cq + 2][p]; v.w = s[4 * cq + 3][p];
        *(float4*)(xTb + (size_t)(p0 + p) * CC + 4 * cq) = v;
    }

    // --- invnorm from the tile: 8 lanes (cq0 groups) per pixel ---
    float sum = 0.0f;
#pragma unroll
    for (int i = 0; i < 8; i++) {
        float v = s[cq0 * 8 + i][p];
        sum += v * v;
    }
    sum += __shfl_xor_sync(0xffffffffu, sum, 1);
    sum += __shfl_xor_sync(0xffffffffu, sum, 2);
    sum += __shfl_xor_sync(0xffffffffu, sum, 4);
    if (cq0 == 0) g_invn[b * PP + p0 + p] = 1.0f / sqrtf(sum);
}

// ---------------------------------------------------------------------------
// 3) simsel: block = 8 pixels of one image row; smem holds the 5x12 halo of
//    NORMALIZED vectors. Warp per pixel; lane l accumulates candidate l's dot
//    serially with a per-lane chunk ROTATION r=(lane-slot)&15 so the 16B
//    granule = (lane+s) mod 8 -> conflict-free LDS.128 every iteration.
//    Top-9-smallest via ordered-int REDUX.MIN + ballot (stable), sorted write.
// ---------------------------------------------------------------------------
#define SROW 68   // smem row stride (floats)

__global__ void __launch_bounds__(256)
simsel2_kernel() {
    __shared__ __align__(16) float sn[60 * SROW];

    const int t = threadIdx.x;
    const int j0 = blockIdx.x * 8;      // 56/8 = 7 exact
    const int i  = blockIdx.y;
    const int b  = blockIdx.z;
    const float* xb   = g_xT + (size_t)b * PP * CC;
    const float* invb = g_invn + b * PP;

    // stage normalized halo: slots (ri 0..4, rj 0..11), rows i-2..i+2, cols j0-2..j0+9
    {
        int slot = t >> 2, q = t & 3;
        if (slot < 60) {
            int ri = slot / 12, rj = slot - ri * 12;
            int gi = i - 2 + ri, gj = j0 - 2 + rj;
            if (gi >= 0 && gi < HH && gj >= 0 && gj < WW) {
                int gp = gi * WW + gj;
                const float* src = xb + (size_t)gp * CC;
                float iv = invb[gp];
                float* dst = sn + slot * SROW;
#pragma unroll
                for (int s = 0; s < 4; s++) {
                    float4 v = *(const float4*)(src + (q + 4 * s) * 4);
                    v.x *= iv; v.y *= iv; v.z *= iv; v.w *= iv;
                    *(float4*)(dst + (q + 4 * s) * 4) = v;
                }
            }
        }
    }
    __syncthreads();

    const int lane = t & 31, w = t >> 5;
    const int j = j0 + w;

    int lo_i = (i - 2 < 0) ? 0 : i - 2;
    int hi_i = (i + 2 > HH - 1) ? HH - 1 : i + 2;
    int lo_j = (j - 2 < 0) ? 0 : j - 2;
    int hi_j = (j + 2 > WW - 1) ? WW - 1 : j + 2;
    int nrow = hi_i - lo_i + 1, ncol = hi_j - lo_j + 1;
    int ncand = nrow * ncol;

    // lane -> (cr, cc) row-major over the clipped window
    unsigned mult = (65536u + (unsigned)ncol - 1) / (unsigned)ncol;
    int cr = (int)(((unsigned)lane * mult) >> 16);
    int cc = lane - cr * ncol;
    int ri = (lo_i - (i - 2)) + cr;
    int rj = (lo_j - (j0 - 2)) + cc;
    int slot = ri * 12 + rj;
    if (lane >= ncand) slot = 0;
    int cpix = (lo_i + cr) * WW + (lo_j + cc);

    const float* crow = sn + slot * SROW;
    const float* prow = sn + (2 * 12 + (w + 2)) * SROW;

    // per-lane rotation: granule = (lane + s) mod 8 -> no bank conflicts
    int idx = (lane - slot) & 15;

    float2 aA = make_float2(0.f, 0.f), aB = make_float2(0.f, 0.f);
#pragma unroll
    for (int s = 0; s < 16; s++) {
        float4 cv = *(const float4*)(crow + 4 * idx);
        float4 pv = *(const float4*)(prow + 4 * idx);
        aA = ffma2(make_float2(cv.x, cv.y), make_float2(pv.x, pv.y), aA);
        aB = ffma2(make_float2(cv.z, cv.w), make_float2(pv.z, pv.w), aB);
        idx = (idx + 1) & 15;
    }
    float sim = (aA.x + aB.x) + (aA.y + aB.y);

    // ordered-int key: monotonic float -> uint
    unsigned ub = __float_as_uint(sim);
    unsigned key = (ub & 0x80000000u) ? ~ub : (ub | 0x80000000u);
    if (lane >= ncand) key = 0xFFFFFFFFu;

    int mypick = 0;
#pragma unroll
    for (int r = 0; r < KK; r++) {
        unsigned m = __reduce_min_sync(0xffffffffu, key);
        unsigned ball = __ballot_sync(0xffffffffu, key == m);
        int bl = __ffs(ball) - 1;
        int wc = __shfl_sync(0xffffffffu, cpix, bl);
        if (lane == bl) key = 0xFFFFFFFFu;
        if (lane == r) mypick = wc;
    }

    int rank = 0;
#pragma unroll
    for (int r = 0; r < KK; r++) {
        int other = __shfl_sync(0xffffffffu, mypick, r);
        if (lane < KK && r != lane && other < mypick) rank++;
    }
    if (lane < KK)
        g_sel[((size_t)(b * PP + i * WW + j)) * KK + rank] = mypick;
}

// ---------------------------------------------------------------------------
// 4) gathered conv as register-blocked SGEMM (unchanged from R5)
// ---------------------------------------------------------------------------
#define GQ 65          // float2 row stride of Gd (pad)
#define SEL_B 2304     // 576 ints
#define WS_B  32768    // 2 x 4096 floats
#define SMEM_TOTAL (SEL_B + WS_B + 2 * 64 * GQ * 8)

__global__ void __launch_bounds__(128)
conv2_kernel(float* __restrict__ out) {
    extern __shared__ char smem_raw[];
    int*    selS  = (int*)smem_raw;
    float*  WsAll = (float*)(smem_raw + SEL_B);
    float2* GdAll = (float2*)(smem_raw + SEL_B + WS_B);

    const int tid = threadIdx.x;
    const int tile = blockIdx.x;
    const int qg0 = tile * 64;
    const int b = tile / 49;
    const int p0 = (tile % 49) * 64;
    const float* xb = g_xT + (size_t)b * PP * CC;

    for (int t = tid; t < 64 * KK; t += 128) selS[t] = g_sel[(size_t)qg0 * KK + t];
    __syncthreads();

    const int u = tid & 15, qr = tid >> 4;

    float4 pg[8];
    auto ldG = [&](int kc) {
#pragma unroll
        for (int ps = 0; ps < 8; ps++) {
            int q = ps * 8 + qr;
            int row = selS[q * KK + kc];
            pg[ps] = *(const float4*)(xb + (size_t)row * CC + u * 4);
        }
    };
    auto stG = [&](int bufi) {
        float2* Gd = GdAll + bufi * (64 * GQ);
#pragma unroll
        for (int ps = 0; ps < 8; ps++) {
            int q = ps * 8 + qr;
            float4 v = pg[ps];
            Gd[(u      ) * GQ + q] = make_float2(v.x, v.x);
            Gd[(16 + u ) * GQ + q] = make_float2(v.y, v.y);
            Gd[(32 + u ) * GQ + q] = make_float2(v.z, v.z);
            Gd[(48 + u ) * GQ + q] = make_float2(v.w, v.w);
        }
    };
    auto cpW = [&](int kc, int bufi) {
        const float* src = g_wP + kc * 4096;
        float* dst = WsAll + bufi * 4096;
#pragma unroll
        for (int i = 0; i < 8; i++) {
            int e = (tid + i * 128) * 4;
            cp16(dst + e, src + e);
        }
        asm volatile("cp.async.commit_group;\n");
    };

    const int w = tid >> 5, l = tid & 31;
    const int o0 = w * 16 + (l >> 4) * 8;
    const int qs = l & 15;

    float2 acc[4][4];
#pragma unroll
    for (int j = 0; j < 4; j++)
#pragma unroll
        for (int i = 0; i < 4; i++) acc[j][i] = make_float2(0.f, 0.f);

    ldG(0);
    cpW(0, 0);

    for (int kc = 0; kc < KK; kc++) {
        int bufi = kc & 1;
        asm volatile("cp.async.wait_group 0;\n");
        stG(bufi);
        __syncthreads();
        if (kc + 1 < KK) {
            ldG(kc + 1);
            cpW(kc + 1, bufi ^ 1);
        }
        const float*  Ws = WsAll + bufi * 4096;
        const float2* Gd = GdAll + bufi * (64 * GQ);
#pragma unroll 8
        for (int m = 0; m < 64; m++) {
            float4 w0 = *(const float4*)(Ws + m * 64 + o0);
            float4 w1 = *(const float4*)(Ws + m * 64 + o0 + 4);
            float2 wp0 = make_float2(w0.x, w0.y);
            float2 wp1 = make_float2(w0.z, w0.w);
            float2 wp2 = make_float2(w1.x, w1.y);
            float2 wp3 = make_float2(w1.z, w1.w);
#pragma unroll
            for (int i = 0; i < 4; i++) {
                float2 g = Gd[m * GQ + qs + 16 * i];
                acc[0][i] = ffma2(wp0, g, acc[0][i]);
                acc[1][i] = ffma2(wp1, g, acc[1][i]);
                acc[2][i] = ffma2(wp2, g, acc[2][i]);
                acc[3][i] = ffma2(wp3, g, acc[3][i]);
            }
        }
        __syncthreads();
    }

    float* ob = out + ((size_t)b * CC) * PP;
#pragma unroll
    for (int j = 0; j < 4; j++) {
        int oa = o0 + 2 * j;
#pragma unroll
        for (int i = 0; i < 4; i++) {
            int p = p0 + qs + 16 * i;
            ob[(size_t)oa * PP + p]       = acc[j][i].x;
            ob[(size_t)(oa + 1) * PP + p] = acc[j][i].y;
        }
    }
}

// ---------------------------------------------------------------------------
extern "C" void kernel_launch(void* const* d_in, const int* in_sizes, int n_in,
                              void* d_out, int out_size) {
    const float* x = (const float*)d_in[0];   // [8,64,56,56]
    const float* w = (const float*)d_in[1];   // [64,64,3,3]
    float* out = (float*)d_out;               // [8,64,56,56]

    cudaFuncSetAttribute(conv2_kernel,
                         cudaFuncAttributeMaxDynamicSharedMemorySize, SMEM_TOTAL);

    prep_kernel<<<793, 256>>>(x, w);
    simsel2_kernel<<<dim3(7, 56, 8), 256>>>();
    conv2_kernel<<<392, 128, SMEM_TOTAL>>>(out);
}

// round 8
// speedup vs baseline: 3.9586x; 1.1226x over previous
#include <cuda_runtime.h>

#define HH 56
#define WW 56
#define PP 3136   // HH*WW
#define BB 8
#define CC 64
#define KK 9      // 3x3

// Scratch (device globals: no allocation allowed in kernel_launch)
__device__ float g_xT[BB * PP * CC];    // x transposed: [b][p][c], c contiguous
__device__ float g_invn[BB * PP];       // 1/||x[b,:,p]||
__device__ int   g_sel[BB * PP * KK];   // sorted selected pixel indices
__device__ float g_wP[KK * 64 * 64];    // W reordered: [k][m][o], c = 4*(m&15)+(m>>4)

// ---------------------------------------------------------------------------
// packed dual-FP32 FMA (Blackwell f32x2 path)
// ---------------------------------------------------------------------------
__device__ __forceinline__ float2 ffma2(float2 a, float2 b, float2 c) {
    unsigned long long A, Bv, Cv;
    A  = *reinterpret_cast<unsigned long long*>(&a);
    Bv = *reinterpret_cast<unsigned long long*>(&b);
    Cv = *reinterpret_cast<unsigned long long*>(&c);
    unsigned long long R;
    asm("fma.rn.f32x2 %0, %1, %2, %3;" : "=l"(R) : "l"(A), "l"(Bv), "l"(Cv));
    return *reinterpret_cast<float2*>(&R);
}

__device__ __forceinline__ void cp16(void* sdst, const void* gsrc) {
    unsigned sa = (unsigned)__cvta_generic_to_shared(sdst);
    asm volatile("cp.async.cg.shared.global [%0], [%1], 16;\n" :: "r"(sa), "l"(gsrc));
}

// ---------------------------------------------------------------------------
// 1) fused prep: blocks [0,784) transpose x[b][c][p] -> xT[b][p][c] AND
//    compute g_invn from the smem tile; blocks [784,793) reorder weights.
// ---------------------------------------------------------------------------
__global__ void __launch_bounds__(256)
prep_kernel(const float* __restrict__ x, const float* __restrict__ wgt) {
    const int id = blockIdx.x;
    const int t = threadIdx.x;

    if (id >= 784) {            // --- wprep: one block per k ---
        int k = id - 784;
#pragma unroll
        for (int i = 0; i < 16; i++) {
            int r = t * 16 + i;            // 0..4095
            int m = r >> 6, o = r & 63;
            int c = 4 * (m & 15) + (m >> 4);
            g_wP[k * 4096 + r] = wgt[o * 576 + c * 9 + k];
        }
        return;
    }

    // --- transpose tile: 32 pixels x 64 channels ---
    __shared__ float s[64][37];
    int b = id / 98, pt = id - b * 98;
    int p0 = pt * 32;
    const float* xb = x + (size_t)b * CC * PP;
    float* xTb = g_xT + (size_t)b * PP * CC;

    int cl = t >> 3;        // 0..31
    int j4 = t & 7;         // float4 column within the 32 pixels
#pragma unroll
    for (int h = 0; h < 2; h++) {
        int c = cl + 32 * h;
        float4 v = *(const float4*)(xb + (size_t)c * PP + p0 + 4 * j4);
        s[c][4 * j4 + 0] = v.x; s[c][4 * j4 + 1] = v.y;
        s[c][4 * j4 + 2] = v.z; s[c][4 * j4 + 3] = v.w;
    }
    __syncthreads();

    int p = t >> 3, cq0 = t & 7;
#pragma unroll
    for (int h = 0; h < 2; h++) {
        int cq = cq0 + 8 * h;
        float4 v;
        v.x = s[4 * cq + 0][p]; v.y = s[4 * cq + 1][p];
        v.z = s[4 * cq + 2][p]; v.w = s[4 * cq + 3][p];
        *(float4*)(xTb + (size_t)(p0 + p) * CC + 4 * cq) = v;
    }

    // --- invnorm from the tile: 8 lanes (cq0 groups) per pixel ---
    float sum = 0.0f;
#pragma unroll
    for (int i = 0; i < 8; i++) {
        float v = s[cq0 * 8 + i][p];
        sum += v * v;
    }
    sum += __shfl_xor_sync(0xffffffffu, sum, 1);
    sum += __shfl_xor_sync(0xffffffffu, sum, 2);
    sum += __shfl_xor_sync(0xffffffffu, sum, 4);
    if (cq0 == 0) g_invn[b * PP + p0 + p] = 1.0f / sqrtf(sum);
}

// ---------------------------------------------------------------------------
// 3) simsel: block = 8 pixels of one image row; smem halo of NORMALIZED
//    vectors stored with per-slot chunk rotation rot=ri (window row):
//    chunk s lives at float4 position (s+ri)&15. Read granule becomes
//    (lane + w + s) mod 8 for interior pixels -> crow conflict-free, while
//    prow (uniform slot per warp) stays a pure broadcast.
//    Top-9-smallest via ordered-int REDUX.MIN + ballot (stable), sorted write.
// ---------------------------------------------------------------------------
#define SROW 68   // smem row stride (floats)

__global__ void __launch_bounds__(256)
simsel2_kernel() {
    __shared__ __align__(16) float sn[60 * SROW];

    const int t = threadIdx.x;
    const int j0 = blockIdx.x * 8;      // 56/8 = 7 exact
    const int i  = blockIdx.y;
    const int b  = blockIdx.z;
    const float* xb   = g_xT + (size_t)b * PP * CC;
    const float* invb = g_invn + b * PP;

    // stage normalized halo with rotation: slots (ri 0..4, rj 0..11)
    {
        int slot = t >> 2, q = t & 3;
        if (slot < 60) {
            int ri = slot / 12, rj = slot - ri * 12;
            int gi = i - 2 + ri, gj = j0 - 2 + rj;
            if (gi >= 0 && gi < HH && gj >= 0 && gj < WW) {
                int gp = gi * WW + gj;
                const float* src = xb + (size_t)gp * CC;
                float iv = invb[gp];
                float* dst = sn + slot * SROW;
#pragma unroll
                for (int s = 0; s < 4; s++) {
                    int chunk = q + 4 * s;
                    float4 v = *(const float4*)(src + chunk * 4);
                    v.x *= iv; v.y *= iv; v.z *= iv; v.w *= iv;
                    *(float4*)(dst + 4 * ((chunk + ri) & 15)) = v;
                }
            }
        }
    }
    __syncthreads();

    const int lane = t & 31, w = t >> 5;
    const int j = j0 + w;

    int lo_i = (i - 2 < 0) ? 0 : i - 2;
    int hi_i = (i + 2 > HH - 1) ? HH - 1 : i + 2;
    int lo_j = (j - 2 < 0) ? 0 : j - 2;
    int hi_j = (j + 2 > WW - 1) ? WW - 1 : j + 2;
    int nrow = hi_i - lo_i + 1, ncol = hi_j - lo_j + 1;
    int ncand = nrow * ncol;

    // lane -> (cr, cc) row-major over the clipped window
    unsigned mult = (65536u + (unsigned)ncol - 1) / (unsigned)ncol;
    int cr = (int)(((unsigned)lane * mult) >> 16);
    int cc = lane - cr * ncol;
    int ri = (lo_i - (i - 2)) + cr;
    int rj = (lo_j - (j0 - 2)) + cc;
    int slot = ri * 12 + rj;
    int rot_c = ri;
    if (lane >= ncand) { slot = 0; rot_c = 0; }
    int cpix = (lo_i + cr) * WW + (lo_j + cc);

    const float* crow = sn + slot * SROW;
    const float* prow = sn + (2 * 12 + (w + 2)) * SROW;   // rot_p = 2

    int idx_c = rot_c & 15;
    int idx_p = 2;

    float2 aA = make_float2(0.f, 0.f), aB = make_float2(0.f, 0.f);
#pragma unroll
    for (int s = 0; s < 16; s++) {
        float4 cv = *(const float4*)(crow + 4 * idx_c);
        float4 pv = *(const float4*)(prow + 4 * idx_p);
        aA = ffma2(make_float2(cv.x, cv.y), make_float2(pv.x, pv.y), aA);
        aB = ffma2(make_float2(cv.z, cv.w), make_float2(pv.z, pv.w), aB);
        idx_c = (idx_c + 1) & 15;
        idx_p = (idx_p + 1) & 15;
    }
    float sim = (aA.x + aB.x) + (aA.y + aB.y);

    // ordered-int key: monotonic float -> uint
    unsigned ub = __float_as_uint(sim);
    unsigned key = (ub & 0x80000000u) ? ~ub : (ub | 0x80000000u);
    if (lane >= ncand) key = 0xFFFFFFFFu;

    int mypick = 0;
#pragma unroll
    for (int r = 0; r < KK; r++) {
        unsigned m = __reduce_min_sync(0xffffffffu, key);
        unsigned ball = __ballot_sync(0xffffffffu, key == m);
        int bl = __ffs(ball) - 1;
        int wc = __shfl_sync(0xffffffffu, cpix, bl);
        if (lane == bl) key = 0xFFFFFFFFu;
        if (lane == r) mypick = wc;
    }

    int rank = 0;
#pragma unroll
    for (int r = 0; r < KK; r++) {
        int other = __shfl_sync(0xffffffffu, mypick, r);
        if (lane < KK && r != lane && other < mypick) rank++;
    }
    if (lane < KK)
        g_sel[((size_t)(b * PP + i * WW + j)) * KK + rank] = mypick;
}

// ---------------------------------------------------------------------------
// 4) gathered conv as register-blocked SGEMM. Gd single-buffered (33KB) so
//    smem drops to ~68KB -> 3 blocks/SM (12 warps) for latency hiding.
// ---------------------------------------------------------------------------
#define GQ 65          // float2 row stride of Gd (pad)
#define SEL_B 2304     // 576 ints
#define WS_B  32768    // 2 x 4096 floats (W stays double-buffered: cp.async)
#define GD_B  (64 * GQ * 8)
#define SMEM_TOTAL (SEL_B + WS_B + GD_B)

__global__ void __launch_bounds__(128)
conv2_kernel(float* __restrict__ out) {
    extern __shared__ char smem_raw[];
    int*    selS  = (int*)smem_raw;
    float*  WsAll = (float*)(smem_raw + SEL_B);
    float2* Gd    = (float2*)(smem_raw + SEL_B + WS_B);

    const int tid = threadIdx.x;
    const int tile = blockIdx.x;
    const int qg0 = tile * 64;
    const int b = tile / 49;
    const int p0 = (tile % 49) * 64;
    const float* xb = g_xT + (size_t)b * PP * CC;

    for (int t = tid; t < 64 * KK; t += 128) selS[t] = g_sel[(size_t)qg0 * KK + t];
    __syncthreads();

    const int u = tid & 15, qr = tid >> 4;

    float4 pg[8];
    auto ldG = [&](int kc) {
#pragma unroll
        for (int ps = 0; ps < 8; ps++) {
            int q = ps * 8 + qr;
            int row = selS[q * KK + kc];
            pg[ps] = *(const float4*)(xb + (size_t)row * CC + u * 4);
        }
    };
    auto stG = [&]() {
#pragma unroll
        for (int ps = 0; ps < 8; ps++) {
            int q = ps * 8 + qr;
            float4 v = pg[ps];
            Gd[(u      ) * GQ + q] = make_float2(v.x, v.x);
            Gd[(16 + u ) * GQ + q] = make_float2(v.y, v.y);
            Gd[(32 + u ) * GQ + q] = make_float2(v.z, v.z);
            Gd[(48 + u ) * GQ + q] = make_float2(v.w, v.w);
        }
    };
    auto cpW = [&](int kc, int bufi) {
        const float* src = g_wP + kc * 4096;
        float* dst = WsAll + bufi * 4096;
#pragma unroll
        for (int i = 0; i < 8; i++) {
            int e = (tid + i * 128) * 4;
            cp16(dst + e, src + e);
        }
        asm volatile("cp.async.commit_group;\n");
    };

    const int w = tid >> 5, l = tid & 31;
    const int o0 = w * 16 + (l >> 4) * 8;
    const int qs = l & 15;

    float2 acc[4][4];
#pragma unroll
    for (int j = 0; j < 4; j++)
#pragma unroll
        for (int i = 0; i < 4; i++) acc[j][i] = make_float2(0.f, 0.f);

    ldG(0);
    cpW(0, 0);

    for (int kc = 0; kc < KK; kc++) {
        int bufi = kc & 1;
        asm volatile("cp.async.wait_group 0;\n");
        stG();                  // prior compute finished (barrier at loop end)
        __syncthreads();        // Gd visible to all warps
        if (kc + 1 < KK) {
            ldG(kc + 1);
            cpW(kc + 1, bufi ^ 1);
        }
        const float* Ws = WsAll + bufi * 4096;
#pragma unroll 8
        for (int m = 0; m < 64; m++) {
            float4 w0 = *(const float4*)(Ws + m * 64 + o0);
            float4 w1 = *(const float4*)(Ws + m * 64 + o0 + 4);
            float2 wp0 = make_float2(w0.x, w0.y);
            float2 wp1 = make_float2(w0.z, w0.w);
            float2 wp2 = make_float2(w1.x, w1.y);
            float2 wp3 = make_float2(w1.z, w1.w);
#pragma unroll
            for (int i = 0; i < 4; i++) {
                float2 g = Gd[m * GQ + qs + 16 * i];
                acc[0][i] = ffma2(wp0, g, acc[0][i]);
                acc[1][i] = ffma2(wp1, g, acc[1][i]);
                acc[2][i] = ffma2(wp2, g, acc[2][i]);
                acc[3][i] = ffma2(wp3, g, acc[3][i]);
            }
        }
        __syncthreads();        // compute done before next stG overwrites Gd
    }

    float* ob = out + ((size_t)b * CC) * PP;
#pragma unroll
    for (int j = 0; j < 4; j++) {
        int oa = o0 + 2 * j;
#pragma unroll
        for (int i = 0; i < 4; i++) {
            int p = p0 + qs + 16 * i;
            ob[(size_t)oa * PP + p]       = acc[j][i].x;
            ob[(size_t)(oa + 1) * PP + p] = acc[j][i].y;
        }
    }
}

// ---------------------------------------------------------------------------
extern "C" void kernel_launch(void* const* d_in, const int* in_sizes, int n_in,
                              void* d_out, int out_size) {
    const float* x = (const float*)d_in[0];   // [8,64,56,56]
    const float* w = (const float*)d_in[1];   // [64,64,3,3]
    float* out = (float*)d_out;               // [8,64,56,56]

    cudaFuncSetAttribute(conv2_kernel,
                         cudaFuncAttributeMaxDynamicSharedMemorySize, SMEM_TOTAL);

    prep_kernel<<<793, 256>>>(x, w);
    simsel2_kernel<<<dim3(7, 56, 8), 256>>>();
    conv2_kernel<<<392, 128, SMEM_TOTAL>>>(out);
}